// round 3
// baseline (speedup 1.0000x reference)
#include <cuda_runtime.h>
#include <cuda_bf16.h>
#include <cstdint>

// Problem constants
#define B_  16
#define S_  64
#define N_  196
#define H_  1024
#define F_  2048
#define E_  512

#define BS_ (B_ * S_)           // 1024
#define BN_ (B_ * N_)           // 3136
#define ATTN_ELEMS (BS_ * F_)   // attn_feats first in d_out

// Scratch (__device__ globals; allocation-free rule)
__device__ float g_hid_c[BS_ * H_];    // tf32-rounded hidden   (4 MB)
__device__ float g_wh_c[H_ * E_];      // tf32-rounded w_h      (2 MB)
__device__ float g_feats_c[BN_ * F_];  // tf32-rounded feats    (25.7 MB)
__device__ float g_wu_c[F_ * E_];      // tf32-rounded w_u      (4 MB)
__device__ float g_Wh[BS_ * E_];       // hidden @ w_h          (2 MB)
__device__ float g_Uv[BN_ * E_];       // feats @ w_u           (6.4 MB)
__device__ float g_wts_c[BS_ * N_];    // tf32-rounded weights  (0.8 MB)

// ---------------------------------------------------------------------------
// tf32 helpers
// ---------------------------------------------------------------------------
__device__ __forceinline__ float tf32r(float f) {
    uint32_t u;
    asm("cvt.rna.tf32.f32 %0, %1;" : "=r"(u) : "f"(f));
    return __uint_as_float(u);
}

__device__ __forceinline__ void mma_tf32(float* c, const uint32_t* a, const uint32_t* b) {
    asm volatile(
        "mma.sync.aligned.m16n8k8.row.col.f32.tf32.tf32.f32 "
        "{%0,%1,%2,%3}, {%4,%5,%6,%7}, {%8,%9}, {%0,%1,%2,%3};"
        : "+f"(c[0]), "+f"(c[1]), "+f"(c[2]), "+f"(c[3])
        : "r"(a[0]), "r"(a[1]), "r"(a[2]), "r"(a[3]), "r"(b[0]), "r"(b[1]));
}

__device__ __forceinline__ void cp_async16(uint32_t smem, const void* gmem, bool pred) {
    int sz = pred ? 16 : 0;
    asm volatile("cp.async.cg.shared.global [%0], [%1], 16, %2;"
                 :: "r"(smem), "l"(gmem), "r"(sz));
}

// ---------------------------------------------------------------------------
// Elementwise tf32 pre-convert (float4 vectorized)
// ---------------------------------------------------------------------------
__global__ __launch_bounds__(256)
void cvt_tf32_kernel(const float4* __restrict__ in, float4* __restrict__ out, int n4) {
    int i = blockIdx.x * 256 + threadIdx.x;
    if (i < n4) {
        float4 v = in[i];
        v.x = tf32r(v.x); v.y = tf32r(v.y); v.z = tf32r(v.z); v.w = tf32r(v.w);
        out[i] = v;
    }
}

// ---------------------------------------------------------------------------
// TF32 tensor-core GEMM (inputs pre-rounded to tf32): C[M,N]=A[M,K]@B[K,N].
// 256 threads, BK=16, 2-stage cp.async. Template on block/warp tile.
// TBN must be 128. K%4==0. Ragged M/K handled by predicates.
// ---------------------------------------------------------------------------
#define BK 16
#define PA 20    // A smem row stride (floats) — conflict-free frag loads
#define PB 136   // B smem row stride (floats)

template<int TBM, int WM, int WN>
__global__ __launch_bounds__(256)
void gemm_tf32(const float* __restrict__ A, const float* __restrict__ B,
               float* __restrict__ C, int M, int N, int K,
               long long sA, long long sB, long long sC) {
    constexpr int TBN = 128;
    constexpr int WARPS_N = TBN / WN;
    constexpr int MI = WM / 16;
    constexpr int NJ = WN / 8;

    A += (long long)blockIdx.z * sA;
    B += (long long)blockIdx.z * sB;
    C += (long long)blockIdx.z * sC;

    __shared__ float As[2][TBM][PA];
    __shared__ float Bs[2][BK][PB];

    const int tid    = threadIdx.x;
    const int wid    = tid >> 5;
    const int lane   = tid & 31;
    const int g      = lane >> 2;
    const int t      = lane & 3;
    const int warp_m = wid / WARPS_N;
    const int warp_n = wid % WARPS_N;
    const int row0   = blockIdx.y * TBM;
    const int col0   = blockIdx.x * TBN;

    const int a_row  = tid >> 2;          // 0..63
    const int a_col  = (tid & 3) << 2;    // 0,4,8,12
    const int b_row0 = tid >> 5;          // 0..7
    const int b_col  = (tid & 31) << 2;   // 0..124

    const int nK = (K + BK - 1) / BK;

    float acc[MI][NJ][4] = {};

    auto load_stage = [&](int stage, int k0) {
        #pragma unroll
        for (int r = a_row; r < TBM; r += 64) {
            int kk = k0 + a_col;
            uint32_t s = (uint32_t)__cvta_generic_to_shared(&As[stage][r][a_col]);
            cp_async16(s, A + (long long)(row0 + r) * K + kk,
                       (row0 + r < M) && (kk < K));
        }
        #pragma unroll
        for (int i = 0; i < 2; i++) {
            int br = b_row0 + i * 8;
            int kk = k0 + br;
            uint32_t s = (uint32_t)__cvta_generic_to_shared(&Bs[stage][br][b_col]);
            cp_async16(s, B + (long long)kk * N + col0 + b_col, kk < K);
        }
    };

    load_stage(0, 0);
    asm volatile("cp.async.commit_group;");

    for (int it = 0; it < nK; it++) {
        int cur = it & 1;
        if (it + 1 < nK) load_stage(cur ^ 1, (it + 1) * BK);
        asm volatile("cp.async.commit_group;");
        asm volatile("cp.async.wait_group 1;");
        __syncthreads();

        #pragma unroll
        for (int k8 = 0; k8 < 2; k8++) {
            const int kb = k8 * 8;
            uint32_t af[MI][4], bf[NJ][2];
            #pragma unroll
            for (int i = 0; i < MI; i++) {
                int rb = warp_m * WM + i * 16;
                af[i][0] = __float_as_uint(As[cur][rb + g    ][kb + t    ]);
                af[i][1] = __float_as_uint(As[cur][rb + g + 8][kb + t    ]);
                af[i][2] = __float_as_uint(As[cur][rb + g    ][kb + t + 4]);
                af[i][3] = __float_as_uint(As[cur][rb + g + 8][kb + t + 4]);
            }
            #pragma unroll
            for (int j = 0; j < NJ; j++) {
                int cb = warp_n * WN + j * 8;
                bf[j][0] = __float_as_uint(Bs[cur][kb + t    ][cb + g]);
                bf[j][1] = __float_as_uint(Bs[cur][kb + t + 4][cb + g]);
            }
            #pragma unroll
            for (int i = 0; i < MI; i++)
                #pragma unroll
                for (int j = 0; j < NJ; j++)
                    mma_tf32(acc[i][j], af[i], bf[j]);
        }
        __syncthreads();
    }

    #pragma unroll
    for (int i = 0; i < MI; i++) {
        #pragma unroll
        for (int j = 0; j < NJ; j++) {
            int r = row0 + warp_m * WM + i * 16 + g;
            int c = col0 + warp_n * WN + j * 8 + 2 * t;
            if (r < M) {
                float2 v0 = make_float2(acc[i][j][0], acc[i][j][1]);
                *reinterpret_cast<float2*>(&C[(long long)r * N + c]) = v0;
            }
            if (r + 8 < M) {
                float2 v1 = make_float2(acc[i][j][2], acc[i][j][3]);
                *reinterpret_cast<float2*>(&C[(long long)(r + 8) * N + c]) = v1;
            }
        }
    }
}

// ---------------------------------------------------------------------------
// Fused scores + mask + softmax with s-grouping (SG=8).
// Block = (b, group of 8 s). 8 warps stride over n; each Uv row is read once
// per block and reused for all 8 queries. Then warp-per-row softmax.
// ---------------------------------------------------------------------------
#define SG 8

__global__ __launch_bounds__(256)
void scores_softmax_kernel(const float* __restrict__ Wh,
                           const float* __restrict__ Uv,
                           const float* __restrict__ bias,
                           const float* __restrict__ w,
                           const int* __restrict__ mask,
                           float* __restrict__ weights,
                           float* __restrict__ wts_c) {
    const int blk  = blockIdx.x;            // 0..127
    const int b    = blk / (S_ / SG);
    const int s0   = (blk % (S_ / SG)) * SG;
    const int tid  = threadIdx.x;
    const int warp = tid >> 5;
    const int lane = tid & 31;

    __shared__ float s_q[SG][E_];           // Wh + bias for 8 queries
    __shared__ float s_sc[SG][N_];
    __shared__ int   s_mask[N_];

    for (int idx = tid; idx < SG * E_; idx += 256) {
        int s = idx >> 9;                   // E_ = 512
        int e = idx & (E_ - 1);
        s_q[s][e] = Wh[(long long)(b * S_ + s0 + s) * E_ + e] + bias[e];
    }
    for (int n = tid; n < N_; n += 256)
        s_mask[n] = mask[b * N_ + n];

    float wreg[16];
    #pragma unroll
    for (int j = 0; j < 16; j++)
        wreg[j] = w[lane + 32 * j];
    __syncthreads();

    for (int n = warp; n < N_; n += 8) {
        const float* uv = Uv + (long long)(b * N_ + n) * E_;
        float uvr[16];
        #pragma unroll
        for (int j = 0; j < 16; j++)
            uvr[j] = uv[lane + 32 * j];

        float acc[SG] = {};
        #pragma unroll
        for (int j = 0; j < 16; j++) {
            const float u  = uvr[j];
            const float wj = wreg[j];
            const int   e  = lane + 32 * j;
            #pragma unroll
            for (int s = 0; s < SG; s++) {
                float tv;
                asm("tanh.approx.f32 %0, %1;" : "=f"(tv) : "f"(s_q[s][e] + u));
                acc[s] = fmaf(wj, tv, acc[s]);
            }
        }
        #pragma unroll
        for (int s = 0; s < SG; s++) {
            float v = acc[s];
            #pragma unroll
            for (int off = 16; off; off >>= 1)
                v += __shfl_xor_sync(0xFFFFFFFFu, v, off);
            if (lane == 0)
                s_sc[s][n] = s_mask[n] ? v : -1e9f;
        }
    }
    __syncthreads();

    // Softmax: warp per s-row over 196 entries (7 strided iters)
    {
        const int s = warp;
        float vals[7];
        float mx = -3.4e38f;
        #pragma unroll
        for (int it = 0; it < 7; it++) {
            int n = lane + 32 * it;
            float v = (n < N_) ? s_sc[s][n] : -3.4e38f;
            vals[it] = v;
            mx = fmaxf(mx, v);
        }
        #pragma unroll
        for (int off = 16; off; off >>= 1)
            mx = fmaxf(mx, __shfl_xor_sync(0xFFFFFFFFu, mx, off));

        float sum = 0.f;
        #pragma unroll
        for (int it = 0; it < 7; it++) {
            int n = lane + 32 * it;
            float ev = (n < N_) ? __expf(vals[it] - mx) : 0.f;
            vals[it] = ev;
            sum += ev;
        }
        #pragma unroll
        for (int off = 16; off; off >>= 1)
            sum += __shfl_xor_sync(0xFFFFFFFFu, sum, off);
        float inv = 1.f / sum;

        const long long base = (long long)(b * S_ + s0 + s) * N_;
        #pragma unroll
        for (int it = 0; it < 7; it++) {
            int n = lane + 32 * it;
            if (n < N_) {
                float wv = vals[it] * inv;
                weights[base + n] = wv;
                wts_c[base + n]   = tf32r(wv);
            }
        }
    }
}

// ---------------------------------------------------------------------------
// Launch
// ---------------------------------------------------------------------------
extern "C" void kernel_launch(void* const* d_in, const int* in_sizes, int n_in,
                              void* d_out, int out_size) {
    const float* hidden = (const float*)d_in[0];   // [16,64,1024]
    const float* feats  = (const float*)d_in[1];   // [16,196,2048]
    const int*   amask  = (const int*)  d_in[2];   // [16,196]
    const float* w_h    = (const float*)d_in[3];   // [1024,512]
    const float* w_u    = (const float*)d_in[4];   // [2048,512]
    const float* bias   = (const float*)d_in[5];   // [512]
    const float* w      = (const float*)d_in[6];   // [512]

    float* out_attn = (float*)d_out;               // [1024, 2048]
    float* out_wts  = (float*)d_out + ATTN_ELEMS;  // [1024, 196]

    float *hid_c, *wh_c, *feats_c, *wu_c, *Wh, *Uv, *wts_c;
    cudaGetSymbolAddress((void**)&hid_c,   g_hid_c);
    cudaGetSymbolAddress((void**)&wh_c,    g_wh_c);
    cudaGetSymbolAddress((void**)&feats_c, g_feats_c);
    cudaGetSymbolAddress((void**)&wu_c,    g_wu_c);
    cudaGetSymbolAddress((void**)&Wh,      g_Wh);
    cudaGetSymbolAddress((void**)&Uv,      g_Uv);
    cudaGetSymbolAddress((void**)&wts_c,   g_wts_c);

    // 0) pre-convert GEMM inputs to tf32-rounded fp32
    auto cvt = [](const float* src, float* dst, int elems) {
        int n4 = elems / 4;
        cvt_tf32_kernel<<<(n4 + 255) / 256, 256>>>(
            (const float4*)src, (float4*)dst, n4);
    };
    cvt(hidden, hid_c,   BS_ * H_);
    cvt(w_h,    wh_c,    H_ * E_);
    cvt(feats,  feats_c, BN_ * F_);
    cvt(w_u,    wu_c,    F_ * E_);

    // 1) Wh = hidden @ w_h : [1024,1024]@[1024,512]   (64x128 tiles)
    {
        dim3 grid(E_ / 128, BS_ / 64, 1);
        gemm_tf32<64, 32, 32><<<grid, 256>>>(hid_c, wh_c, Wh, BS_, E_, H_, 0, 0, 0);
    }
    // 2) Uv = feats @ w_u : [3136,2048]@[2048,512]    (128x128 tiles, 64x32 warps)
    {
        dim3 grid(E_ / 128, (BN_ + 127) / 128, 1);
        gemm_tf32<128, 64, 32><<<grid, 256>>>(feats_c, wu_c, Uv, BN_, E_, F_, 0, 0, 0);
    }
    // 3) fused scores + mask + softmax -> weights (+ tf32 shadow)
    scores_softmax_kernel<<<B_ * (S_ / SG), 256>>>(Wh, Uv, bias, w, amask,
                                                   out_wts, wts_c);
    // 4) attn_feats[b] = weights[b] @ feats[b] : [64,196]@[196,2048] batched
    {
        dim3 grid(F_ / 128, 1, B_);
        gemm_tf32<64, 32, 32><<<grid, 256>>>(wts_c, feats_c, out_attn, S_, F_, N_,
                                             (long long)S_ * N_,
                                             (long long)N_ * F_,
                                             (long long)S_ * F_);
    }
}

// round 4
// speedup vs baseline: 1.1843x; 1.1843x over previous
#include <cuda_runtime.h>
#include <cuda_bf16.h>
#include <cstdint>

// Problem constants
#define B_  16
#define S_  64
#define N_  196
#define H_  1024
#define F_  2048
#define E_  512

#define BS_ (B_ * S_)           // 1024
#define BN_ (B_ * N_)           // 3136
#define ATTN_ELEMS (BS_ * F_)   // attn_feats first in d_out

// Scratch (__device__ globals; allocation-free rule)
__device__ float g_Wh[BS_ * E_];   // 2 MB
__device__ float g_Uv[BN_ * E_];   // 6.4 MB

#define BK 16
#define PA 20    // A smem row stride: frag banks (20g+t)%32 all distinct
#define PB 132   // B smem row stride: frag banks (4t+g)%32 all distinct

__device__ __forceinline__ uint32_t f2tf32(float f) {
    uint32_t u;
    asm("cvt.rna.tf32.f32 %0, %1;" : "=r"(u) : "f"(f));
    return u;
}

__device__ __forceinline__ void mma_tf32(float* c, const uint32_t* a, const uint32_t* b) {
    asm volatile(
        "mma.sync.aligned.m16n8k8.row.col.f32.tf32.tf32.f32 "
        "{%0,%1,%2,%3}, {%4,%5,%6,%7}, {%8,%9}, {%0,%1,%2,%3};"
        : "+f"(c[0]), "+f"(c[1]), "+f"(c[2]), "+f"(c[3])
        : "r"(a[0]), "r"(a[1]), "r"(a[2]), "r"(a[3]), "r"(b[0]), "r"(b[1]));
}

__device__ __forceinline__ void cp_async16(uint32_t smem, const void* gmem, bool pred) {
    int sz = pred ? 16 : 0;
    asm volatile("cp.async.cg.shared.global [%0], [%1], 16, %2;"
                 :: "r"(smem), "l"(gmem), "r"(sz));
}

// ---------------------------------------------------------------------------
// TF32 tensor-core GEMM: C[M,N] = A[M,K] @ B[K,N], row-major, fp32 in/out.
// In-fragment tf32 rounding, STAGES-deep cp.async pipeline, dynamic smem.
// TBN=128 fixed. N%128==0 required; ragged M/K predicated.
// ---------------------------------------------------------------------------
template<int TBM, int WM, int WN, int THREADS, int STAGES>
__global__ __launch_bounds__(THREADS)
void gemm_tf32(const float* __restrict__ A, const float* __restrict__ B,
               float* __restrict__ C, int M, int N, int K,
               long long sA, long long sB, long long sC) {
    constexpr int TBN = 128;
    constexpr int WARPS_N = TBN / WN;
    constexpr int MI = WM / 16;
    constexpr int NJ = WN / 8;
    constexpr int AR = THREADS / 4;    // A rows loaded per pass
    constexpr int BR = THREADS / 32;   // B rows loaded per pass

    A += (long long)blockIdx.z * sA;
    B += (long long)blockIdx.z * sB;
    C += (long long)blockIdx.z * sC;

    extern __shared__ float smem[];
    float* As = smem;                         // [STAGES][TBM][PA]
    float* Bs = smem + STAGES * TBM * PA;     // [STAGES][BK][PB]

    const int tid    = threadIdx.x;
    const int wid    = tid >> 5;
    const int lane   = tid & 31;
    const int g      = lane >> 2;
    const int t      = lane & 3;
    const int warp_m = wid / WARPS_N;
    const int warp_n = wid % WARPS_N;
    const int row0   = blockIdx.y * TBM;
    const int col0   = blockIdx.x * TBN;

    const int a_row = tid >> 2;
    const int a_col = (tid & 3) << 2;
    const int b_row = tid >> 5;
    const int b_col = (tid & 31) << 2;

    const int nK = (K + BK - 1) / BK;

    float acc[MI][NJ][4] = {};

    auto load_stage = [&](int st, int k0) {
        float* as = As + st * TBM * PA;
        float* bs = Bs + st * BK * PB;
        #pragma unroll
        for (int r = a_row; r < TBM; r += AR) {
            int kk = k0 + a_col;
            uint32_t s = (uint32_t)__cvta_generic_to_shared(&as[r * PA + a_col]);
            cp_async16(s, A + (long long)(row0 + r) * K + kk,
                       (row0 + r < M) && (kk < K));
        }
        #pragma unroll
        for (int br = b_row; br < BK; br += BR) {
            int kk = k0 + br;
            uint32_t s = (uint32_t)__cvta_generic_to_shared(&bs[br * PB + b_col]);
            cp_async16(s, B + (long long)kk * N + col0 + b_col, kk < K);
        }
    };

    #pragma unroll
    for (int s = 0; s < STAGES - 1; s++) {
        if (s < nK) load_stage(s, s * BK);
        asm volatile("cp.async.commit_group;");
    }

    for (int it = 0; it < nK; it++) {
        asm volatile("cp.async.wait_group %0;" :: "n"(STAGES - 2));
        __syncthreads();

        int lds = it + STAGES - 1;
        if (lds < nK) load_stage(lds % STAGES, lds * BK);
        asm volatile("cp.async.commit_group;");

        const float* as = As + (it % STAGES) * TBM * PA;
        const float* bs = Bs + (it % STAGES) * BK * PB;

        #pragma unroll
        for (int k8 = 0; k8 < 2; k8++) {
            const int kb = k8 * 8;
            uint32_t af[MI][4], bf[NJ][2];
            #pragma unroll
            for (int i = 0; i < MI; i++) {
                int rb = warp_m * WM + i * 16;
                af[i][0] = f2tf32(as[(rb + g    ) * PA + kb + t    ]);
                af[i][1] = f2tf32(as[(rb + g + 8) * PA + kb + t    ]);
                af[i][2] = f2tf32(as[(rb + g    ) * PA + kb + t + 4]);
                af[i][3] = f2tf32(as[(rb + g + 8) * PA + kb + t + 4]);
            }
            #pragma unroll
            for (int j = 0; j < NJ; j++) {
                int cb = warp_n * WN + j * 8;
                bf[j][0] = f2tf32(bs[(kb + t    ) * PB + cb + g]);
                bf[j][1] = f2tf32(bs[(kb + t + 4) * PB + cb + g]);
            }
            #pragma unroll
            for (int i = 0; i < MI; i++)
                #pragma unroll
                for (int j = 0; j < NJ; j++)
                    mma_tf32(acc[i][j], af[i], bf[j]);
        }
        __syncthreads();
    }

    #pragma unroll
    for (int i = 0; i < MI; i++) {
        #pragma unroll
        for (int j = 0; j < NJ; j++) {
            int r = row0 + warp_m * WM + i * 16 + g;
            int c = col0 + warp_n * WN + j * 8 + 2 * t;
            if (r < M) {
                float2 v0 = make_float2(acc[i][j][0], acc[i][j][1]);
                *reinterpret_cast<float2*>(&C[(long long)r * N + c]) = v0;
            }
            if (r + 8 < M) {
                float2 v1 = make_float2(acc[i][j][2], acc[i][j][3]);
                *reinterpret_cast<float2*>(&C[(long long)(r + 8) * N + c]) = v1;
            }
        }
    }
}

// ---------------------------------------------------------------------------
// Fused scores + mask + softmax, SG=4 queries per block (256 blocks).
// 8 warps stride over n; each Uv row read once per block, reused 4x.
// ---------------------------------------------------------------------------
#define SG 4

__global__ __launch_bounds__(256)
void scores_softmax_kernel(const float* __restrict__ Wh,
                           const float* __restrict__ Uv,
                           const float* __restrict__ bias,
                           const float* __restrict__ w,
                           const int* __restrict__ mask,
                           float* __restrict__ weights) {
    const int blk  = blockIdx.x;            // 0..255
    const int b    = blk / (S_ / SG);
    const int s0   = (blk % (S_ / SG)) * SG;
    const int tid  = threadIdx.x;
    const int warp = tid >> 5;
    const int lane = tid & 31;

    __shared__ float s_q[SG][E_];
    __shared__ float s_sc[SG][N_];
    __shared__ int   s_mask[N_];

    for (int idx = tid; idx < SG * E_; idx += 256) {
        int s = idx >> 9;                   // E_ = 512
        int e = idx & (E_ - 1);
        s_q[s][e] = Wh[(long long)(b * S_ + s0 + s) * E_ + e] + bias[e];
    }
    for (int n = tid; n < N_; n += 256)
        s_mask[n] = mask[b * N_ + n];

    float wreg[16];
    #pragma unroll
    for (int j = 0; j < 16; j++)
        wreg[j] = w[lane + 32 * j];
    __syncthreads();

    for (int n = warp; n < N_; n += 8) {
        const float* uv = Uv + (long long)(b * N_ + n) * E_;
        float uvr[16];
        #pragma unroll
        for (int j = 0; j < 16; j++)
            uvr[j] = uv[lane + 32 * j];

        float acc[SG] = {};
        #pragma unroll
        for (int j = 0; j < 16; j++) {
            const float u  = uvr[j];
            const float wj = wreg[j];
            const int   e  = lane + 32 * j;
            #pragma unroll
            for (int s = 0; s < SG; s++) {
                float tv;
                asm("tanh.approx.f32 %0, %1;" : "=f"(tv) : "f"(s_q[s][e] + u));
                acc[s] = fmaf(wj, tv, acc[s]);
            }
        }
        #pragma unroll
        for (int s = 0; s < SG; s++) {
            float v = acc[s];
            #pragma unroll
            for (int off = 16; off; off >>= 1)
                v += __shfl_xor_sync(0xFFFFFFFFu, v, off);
            if (lane == 0)
                s_sc[s][n] = s_mask[n] ? v : -1e9f;
        }
    }
    __syncthreads();

    // Softmax: warp per s-row (warps 0..SG-1)
    if (warp < SG) {
        const int s = warp;
        float vals[7];
        float mx = -3.4e38f;
        #pragma unroll
        for (int it = 0; it < 7; it++) {
            int n = lane + 32 * it;
            float v = (n < N_) ? s_sc[s][n] : -3.4e38f;
            vals[it] = v;
            mx = fmaxf(mx, v);
        }
        #pragma unroll
        for (int off = 16; off; off >>= 1)
            mx = fmaxf(mx, __shfl_xor_sync(0xFFFFFFFFu, mx, off));

        float sum = 0.f;
        #pragma unroll
        for (int it = 0; it < 7; it++) {
            int n = lane + 32 * it;
            float ev = (n < N_) ? __expf(vals[it] - mx) : 0.f;
            vals[it] = ev;
            sum += ev;
        }
        #pragma unroll
        for (int off = 16; off; off >>= 1)
            sum += __shfl_xor_sync(0xFFFFFFFFu, sum, off);
        float inv = 1.f / sum;

        const long long base = (long long)(b * S_ + s0 + s) * N_;
        #pragma unroll
        for (int it = 0; it < 7; it++) {
            int n = lane + 32 * it;
            if (n < N_)
                weights[base + n] = vals[it] * inv;
        }
    }
}

// ---------------------------------------------------------------------------
// Launch
// ---------------------------------------------------------------------------
extern "C" void kernel_launch(void* const* d_in, const int* in_sizes, int n_in,
                              void* d_out, int out_size) {
    const float* hidden = (const float*)d_in[0];   // [16,64,1024]
    const float* feats  = (const float*)d_in[1];   // [16,196,2048]
    const int*   amask  = (const int*)  d_in[2];   // [16,196]
    const float* w_h    = (const float*)d_in[3];   // [1024,512]
    const float* w_u    = (const float*)d_in[4];   // [2048,512]
    const float* bias   = (const float*)d_in[5];   // [512]
    const float* w      = (const float*)d_in[6];   // [512]

    float* out_attn = (float*)d_out;               // [1024, 2048]
    float* out_wts  = (float*)d_out + ATTN_ELEMS;  // [1024, 196]

    float *Wh, *Uv;
    cudaGetSymbolAddress((void**)&Wh, g_Wh);
    cudaGetSymbolAddress((void**)&Uv, g_Uv);

    constexpr int SMEM_64  = (4 * 64  * PA + 4 * BK * PB) * 4;  // 54272
    constexpr int SMEM_128 = (4 * 128 * PA + 4 * BK * PB) * 4;  // 74752

    static bool attr_set = false;
    if (!attr_set) {
        cudaFuncSetAttribute(gemm_tf32<64, 64, 32, 128, 4>,
                             cudaFuncAttributeMaxDynamicSharedMemorySize, SMEM_64);
        cudaFuncSetAttribute(gemm_tf32<128, 64, 32, 256, 4>,
                             cudaFuncAttributeMaxDynamicSharedMemorySize, SMEM_128);
        attr_set = true;
    }

    // 1) Wh = hidden @ w_h : [1024,1024]@[1024,512]
    {
        dim3 grid(E_ / 128, BS_ / 64, 1);
        gemm_tf32<64, 64, 32, 128, 4><<<grid, 128, SMEM_64>>>(
            hidden, w_h, Wh, BS_, E_, H_, 0, 0, 0);
    }
    // 2) Uv = feats @ w_u : [3136,2048]@[2048,512]
    {
        dim3 grid(E_ / 128, (BN_ + 127) / 128, 1);
        gemm_tf32<128, 64, 32, 256, 4><<<grid, 256, SMEM_128>>>(
            feats, w_u, Uv, BN_, E_, F_, 0, 0, 0);
    }
    // 3) fused scores + mask + softmax -> weights
    scores_softmax_kernel<<<B_ * (S_ / SG), 256>>>(Wh, Uv, bias, w, amask, out_wts);

    // 4) attn_feats[b] = weights[b] @ feats[b] : [64,196]@[196,2048] batched
    {
        dim3 grid(F_ / 128, 1, B_);
        gemm_tf32<64, 64, 32, 128, 4><<<grid, 128, SMEM_64>>>(
            out_wts, feats, out_attn, S_, F_, N_,
            (long long)S_ * N_,
            (long long)N_ * F_,
            (long long)S_ * F_);
    }
}

// round 5
// speedup vs baseline: 1.2200x; 1.0301x over previous
#include <cuda_runtime.h>
#include <cuda_bf16.h>
#include <cstdint>

// Problem constants
#define B_  16
#define S_  64
#define N_  196
#define H_  1024
#define F_  2048
#define E_  512

#define BS_ (B_ * S_)           // 1024
#define BN_ (B_ * N_)           // 3136 = 49*64
#define ATTN_ELEMS (BS_ * F_)   // attn_feats first in d_out

// Scratch (__device__ globals; allocation-free rule)
__device__ float g_Wh[BS_ * E_];   // 2 MB
__device__ float g_Uv[BN_ * E_];   // 6.4 MB

#define BK 16
#define PA 20    // A smem row stride: frag banks (20g+t)%32 all distinct
#define PB 132   // B smem row stride: frag banks (4t+g)%32 all distinct

__device__ __forceinline__ uint32_t f2tf32(float f) {
    uint32_t u;
    asm("cvt.rna.tf32.f32 %0, %1;" : "=r"(u) : "f"(f));
    return u;
}

__device__ __forceinline__ void mma_tf32(float* c, const uint32_t* a, const uint32_t* b) {
    asm volatile(
        "mma.sync.aligned.m16n8k8.row.col.f32.tf32.tf32.f32 "
        "{%0,%1,%2,%3}, {%4,%5,%6,%7}, {%8,%9}, {%0,%1,%2,%3};"
        : "+f"(c[0]), "+f"(c[1]), "+f"(c[2]), "+f"(c[3])
        : "r"(a[0]), "r"(a[1]), "r"(a[2]), "r"(a[3]), "r"(b[0]), "r"(b[1]));
}

__device__ __forceinline__ void cp_async16(uint32_t smem, const void* gmem, bool pred) {
    int sz = pred ? 16 : 0;
    asm volatile("cp.async.cg.shared.global [%0], [%1], 16, %2;"
                 :: "r"(smem), "l"(gmem), "r"(sz));
}

// ---------------------------------------------------------------------------
// Core GEMM tile routine: computes C[row0:row0+TBM, col0:col0+128] for
// C = A[M,K] @ B[K,N] (row-major). tf32 rounding in fragment loads.
// THREADS=64 (2 warps), warp tile WMxWN covering TBMx128.
// ---------------------------------------------------------------------------
template<int TBM, int WM, int WN, int THREADS, int STAGES>
__device__ __forceinline__
void gemm_core(const float* __restrict__ A, const float* __restrict__ B,
               float* __restrict__ C, int M, int N, int K,
               int row0, int col0, float* smem) {
    constexpr int TBN = 128;
    constexpr int WARPS_N = TBN / WN;
    constexpr int MI = WM / 16;
    constexpr int NJ = WN / 8;
    constexpr int AR = THREADS / 4;
    constexpr int BR = THREADS / 32;

    float* As = smem;                         // [STAGES][TBM][PA]
    float* Bs = smem + STAGES * TBM * PA;     // [STAGES][BK][PB]

    const int tid    = threadIdx.x;
    const int wid    = tid >> 5;
    const int lane   = tid & 31;
    const int g      = lane >> 2;
    const int t      = lane & 3;
    const int warp_m = wid / WARPS_N;
    const int warp_n = wid % WARPS_N;

    const int a_row = tid >> 2;
    const int a_col = (tid & 3) << 2;
    const int b_row = tid >> 5;
    const int b_col = (tid & 31) << 2;

    const int nK = (K + BK - 1) / BK;

    float acc[MI][NJ][4] = {};

    auto load_stage = [&](int st, int k0) {
        float* as = As + st * TBM * PA;
        float* bs = Bs + st * BK * PB;
        #pragma unroll
        for (int r = a_row; r < TBM; r += AR) {
            int kk = k0 + a_col;
            uint32_t s = (uint32_t)__cvta_generic_to_shared(&as[r * PA + a_col]);
            cp_async16(s, A + (long long)(row0 + r) * K + kk,
                       (row0 + r < M) && (kk < K));
        }
        #pragma unroll
        for (int br = b_row; br < BK; br += BR) {
            int kk = k0 + br;
            uint32_t s = (uint32_t)__cvta_generic_to_shared(&bs[br * PB + b_col]);
            cp_async16(s, B + (long long)kk * N + col0 + b_col, kk < K);
        }
    };

    #pragma unroll
    for (int s = 0; s < STAGES - 1; s++) {
        if (s < nK) load_stage(s, s * BK);
        asm volatile("cp.async.commit_group;");
    }

    for (int it = 0; it < nK; it++) {
        asm volatile("cp.async.wait_group %0;" :: "n"(STAGES - 2));
        __syncthreads();

        int lds = it + STAGES - 1;
        if (lds < nK) load_stage(lds % STAGES, lds * BK);
        asm volatile("cp.async.commit_group;");

        const float* as = As + (it % STAGES) * TBM * PA;
        const float* bs = Bs + (it % STAGES) * BK * PB;

        #pragma unroll
        for (int k8 = 0; k8 < 2; k8++) {
            const int kb = k8 * 8;
            uint32_t af[MI][4], bf[NJ][2];
            #pragma unroll
            for (int i = 0; i < MI; i++) {
                int rb = warp_m * WM + i * 16;
                af[i][0] = f2tf32(as[(rb + g    ) * PA + kb + t    ]);
                af[i][1] = f2tf32(as[(rb + g + 8) * PA + kb + t    ]);
                af[i][2] = f2tf32(as[(rb + g    ) * PA + kb + t + 4]);
                af[i][3] = f2tf32(as[(rb + g + 8) * PA + kb + t + 4]);
            }
            #pragma unroll
            for (int j = 0; j < NJ; j++) {
                int cb = warp_n * WN + j * 8;
                bf[j][0] = f2tf32(bs[(kb + t    ) * PB + cb + g]);
                bf[j][1] = f2tf32(bs[(kb + t + 4) * PB + cb + g]);
            }
            #pragma unroll
            for (int i = 0; i < MI; i++)
                #pragma unroll
                for (int j = 0; j < NJ; j++)
                    mma_tf32(acc[i][j], af[i], bf[j]);
        }
        __syncthreads();
    }

    #pragma unroll
    for (int i = 0; i < MI; i++) {
        #pragma unroll
        for (int j = 0; j < NJ; j++) {
            int r = row0 + warp_m * WM + i * 16 + g;
            int c = col0 + warp_n * WN + j * 8 + 2 * t;
            if (r < M) {
                float2 v0 = make_float2(acc[i][j][0], acc[i][j][1]);
                *reinterpret_cast<float2*>(&C[(long long)r * N + c]) = v0;
            }
            if (r + 8 < M) {
                float2 v1 = make_float2(acc[i][j][2], acc[i][j][3]);
                *reinterpret_cast<float2*>(&C[(long long)(r + 8) * N + c]) = v1;
            }
        }
    }
}

// Single-problem batched wrapper (used for attn GEMM)
template<int TBM, int WM, int WN, int THREADS, int STAGES>
__global__ __launch_bounds__(THREADS)
void gemm_single(const float* __restrict__ A, const float* __restrict__ B,
                 float* __restrict__ C, int M, int N, int K,
                 long long sA, long long sB, long long sC) {
    extern __shared__ float smem[];
    gemm_core<TBM, WM, WN, THREADS, STAGES>(
        A + (long long)blockIdx.z * sA,
        B + (long long)blockIdx.z * sB,
        C + (long long)blockIdx.z * sC,
        M, N, K, blockIdx.y * TBM, blockIdx.x * 128, smem);
}

// Dual-problem wrapper: blocks [0, nb1) -> problem 1, rest -> problem 2.
// Both share N (=512) and tile config. Removes wave-quantization gap.
template<int TBM, int WM, int WN, int THREADS, int STAGES>
__global__ __launch_bounds__(THREADS)
void gemm_dual(const float* __restrict__ A1, const float* __restrict__ B1,
               float* __restrict__ C1, int M1, int K1, int nb1,
               const float* __restrict__ A2, const float* __restrict__ B2,
               float* __restrict__ C2, int M2, int K2, int N) {
    extern __shared__ float smem[];
    constexpr int CB = 4;   // N=512 -> 4 col blocks of 128
    int bx = blockIdx.x;
    if (bx < nb1) {
        gemm_core<TBM, WM, WN, THREADS, STAGES>(
            A1, B1, C1, M1, N, K1, (bx / CB) * TBM, (bx % CB) * 128, smem);
    } else {
        bx -= nb1;
        gemm_core<TBM, WM, WN, THREADS, STAGES>(
            A2, B2, C2, M2, N, K2, (bx / CB) * TBM, (bx % CB) * 128, smem);
    }
}

// ---------------------------------------------------------------------------
// Fused scores + mask + softmax, SG=4 queries per block (256 blocks).
// ---------------------------------------------------------------------------
#define SG 4

__global__ __launch_bounds__(256)
void scores_softmax_kernel(const float* __restrict__ Wh,
                           const float* __restrict__ Uv,
                           const float* __restrict__ bias,
                           const float* __restrict__ w,
                           const int* __restrict__ mask,
                           float* __restrict__ weights) {
    const int blk  = blockIdx.x;
    const int b    = blk / (S_ / SG);
    const int s0   = (blk % (S_ / SG)) * SG;
    const int tid  = threadIdx.x;
    const int warp = tid >> 5;
    const int lane = tid & 31;

    __shared__ float s_q[SG][E_];
    __shared__ float s_sc[SG][N_];
    __shared__ int   s_mask[N_];

    for (int idx = tid; idx < SG * E_; idx += 256) {
        int s = idx >> 9;
        int e = idx & (E_ - 1);
        s_q[s][e] = Wh[(long long)(b * S_ + s0 + s) * E_ + e] + bias[e];
    }
    for (int n = tid; n < N_; n += 256)
        s_mask[n] = mask[b * N_ + n];

    float wreg[16];
    #pragma unroll
    for (int j = 0; j < 16; j++)
        wreg[j] = w[lane + 32 * j];
    __syncthreads();

    for (int n = warp; n < N_; n += 8) {
        const float* uv = Uv + (long long)(b * N_ + n) * E_;
        float uvr[16];
        #pragma unroll
        for (int j = 0; j < 16; j++)
            uvr[j] = uv[lane + 32 * j];

        float acc[SG] = {};
        #pragma unroll
        for (int j = 0; j < 16; j++) {
            const float u  = uvr[j];
            const float wj = wreg[j];
            const int   e  = lane + 32 * j;
            #pragma unroll
            for (int s = 0; s < SG; s++) {
                float tv;
                asm("tanh.approx.f32 %0, %1;" : "=f"(tv) : "f"(s_q[s][e] + u));
                acc[s] = fmaf(wj, tv, acc[s]);
            }
        }
        #pragma unroll
        for (int s = 0; s < SG; s++) {
            float v = acc[s];
            #pragma unroll
            for (int off = 16; off; off >>= 1)
                v += __shfl_xor_sync(0xFFFFFFFFu, v, off);
            if (lane == 0)
                s_sc[s][n] = s_mask[n] ? v : -1e9f;
        }
    }
    __syncthreads();

    if (warp < SG) {
        const int s = warp;
        float vals[7];
        float mx = -3.4e38f;
        #pragma unroll
        for (int it = 0; it < 7; it++) {
            int n = lane + 32 * it;
            float v = (n < N_) ? s_sc[s][n] : -3.4e38f;
            vals[it] = v;
            mx = fmaxf(mx, v);
        }
        #pragma unroll
        for (int off = 16; off; off >>= 1)
            mx = fmaxf(mx, __shfl_xor_sync(0xFFFFFFFFu, mx, off));

        float sum = 0.f;
        #pragma unroll
        for (int it = 0; it < 7; it++) {
            int n = lane + 32 * it;
            float ev = (n < N_) ? __expf(vals[it] - mx) : 0.f;
            vals[it] = ev;
            sum += ev;
        }
        #pragma unroll
        for (int off = 16; off; off >>= 1)
            sum += __shfl_xor_sync(0xFFFFFFFFu, sum, off);
        float inv = 1.f / sum;

        const long long base = (long long)(b * S_ + s0 + s) * N_;
        #pragma unroll
        for (int it = 0; it < 7; it++) {
            int n = lane + 32 * it;
            if (n < N_)
                weights[base + n] = vals[it] * inv;
        }
    }
}

// ---------------------------------------------------------------------------
// Launch
// ---------------------------------------------------------------------------
extern "C" void kernel_launch(void* const* d_in, const int* in_sizes, int n_in,
                              void* d_out, int out_size) {
    const float* hidden = (const float*)d_in[0];   // [16,64,1024]
    const float* feats  = (const float*)d_in[1];   // [16,196,2048]
    const int*   amask  = (const int*)  d_in[2];   // [16,196]
    const float* w_h    = (const float*)d_in[3];   // [1024,512]
    const float* w_u    = (const float*)d_in[4];   // [2048,512]
    const float* bias   = (const float*)d_in[5];   // [512]
    const float* w      = (const float*)d_in[6];   // [512]

    float* out_attn = (float*)d_out;               // [1024, 2048]
    float* out_wts  = (float*)d_out + ATTN_ELEMS;  // [1024, 196]

    float *Wh, *Uv;
    cudaGetSymbolAddress((void**)&Wh, g_Wh);
    cudaGetSymbolAddress((void**)&Uv, g_Uv);

    // TBM=64, warp 64x64, 64 threads, 4 stages
    constexpr int STG = 4;
    constexpr int SMEM = STG * (64 * PA + BK * PB) * 4;  // 54272 B

    static bool attr_set = false;
    if (!attr_set) {
        cudaFuncSetAttribute(gemm_dual<64, 64, 64, 64, STG>,
                             cudaFuncAttributeMaxDynamicSharedMemorySize, SMEM);
        cudaFuncSetAttribute(gemm_single<64, 64, 64, 64, STG>,
                             cudaFuncAttributeMaxDynamicSharedMemorySize, SMEM);
        attr_set = true;
    }

    // 1+2) Fused launch: Uv = feats @ w_u (196 blocks) + Wh = hidden @ w_h (64 blocks)
    {
        int nb_uv = (BN_ / 64) * 4;   // 49*4 = 196
        int nb_wh = (BS_ / 64) * 4;   // 16*4 = 64
        gemm_dual<64, 64, 64, 64, STG><<<nb_uv + nb_wh, 64, SMEM>>>(
            feats,  w_u, Uv, BN_, F_, nb_uv,
            hidden, w_h, Wh, BS_, H_, E_);
    }
    // 3) fused scores + mask + softmax -> weights
    scores_softmax_kernel<<<B_ * (S_ / SG), 256>>>(Wh, Uv, bias, w, amask, out_wts);

    // 4) attn_feats[b] = weights[b] @ feats[b] : [64,196]@[196,2048] batched
    {
        dim3 grid(F_ / 128, 1, B_);
        gemm_single<64, 64, 64, 64, STG><<<grid, 64, SMEM>>>(
            out_wts, feats, out_attn, S_, F_, N_,
            (long long)S_ * N_,
            (long long)N_ * F_,
            (long long)S_ * F_);
    }
}

// round 7
// speedup vs baseline: 1.6133x; 1.3224x over previous
#include <cuda_runtime.h>
#include <cuda_bf16.h>
#include <cstdint>

// Problem constants
#define B_  16
#define S_  64
#define N_  196
#define H_  1024
#define F_  2048
#define E_  512

#define BS_ (B_ * S_)           // 1024
#define BN_ (B_ * N_)           // 3136 = 49*64
#define ATTN_ELEMS (BS_ * F_)   // attn_feats first in d_out

#define KSPLIT 4                // Uv split-K factor (2048/4 = 512)

// Scratch (__device__ globals; allocation-free rule)
__device__ float g_Wh[BS_ * E_];             // 2 MB
__device__ float g_Uv[BN_ * E_];             // 6.4 MB
__device__ float g_UvP[KSPLIT][BN_ * E_];    // 25.6 MB split-K partials
__device__ float g_wu_c[F_ * E_];            // tf32-rounded w_u (4 MB)
__device__ float g_wh_c[H_ * E_];            // tf32-rounded w_h (2 MB)
__device__ float g_wts_c[BS_ * N_];          // tf32-rounded weights (0.8 MB)

#define BK 16
#define PA 20    // A smem row stride: frag banks conflict-free
#define PB 132   // B smem row stride: frag banks conflict-free

__device__ __forceinline__ uint32_t f2tf32(float f) {
    uint32_t u;
    asm("cvt.rna.tf32.f32 %0, %1;" : "=r"(u) : "f"(f));
    return u;
}

__device__ __forceinline__ void mma_tf32(float* c, const uint32_t* a, const uint32_t* b) {
    asm volatile(
        "mma.sync.aligned.m16n8k8.row.col.f32.tf32.tf32.f32 "
        "{%0,%1,%2,%3}, {%4,%5,%6,%7}, {%8,%9}, {%0,%1,%2,%3};"
        : "+f"(c[0]), "+f"(c[1]), "+f"(c[2]), "+f"(c[3])
        : "r"(a[0]), "r"(a[1]), "r"(a[2]), "r"(a[3]), "r"(b[0]), "r"(b[1]));
}

__device__ __forceinline__ void cp_async16(uint32_t smem, const void* gmem, bool pred) {
    int sz = pred ? 16 : 0;
    asm volatile("cp.async.cg.shared.global [%0], [%1], 16, %2;"
                 :: "r"(smem), "l"(gmem), "r"(sz));
}

// ---------------------------------------------------------------------------
// Core GEMM tile: C[row0:+TBM, col0:+128] = A[M x lda] @ B[K x N] (row-major).
// RA/RB: apply tf32 rounding on A/B fragment loads (false = pre-rounded).
// Keff = K extent processed; lda = A row stride (split-K: lda > Keff).
// ---------------------------------------------------------------------------
template<int TBM, int WM, int WN, int THREADS, int STAGES, bool RA, bool RB>
__device__ __forceinline__
void gemm_core(const float* __restrict__ A, const float* __restrict__ B,
               float* __restrict__ C, int M, int N, int Keff, int lda,
               int row0, int col0, float* smem) {
    constexpr int TBN = 128;
    constexpr int WARPS_N = TBN / WN;
    constexpr int MI = WM / 16;
    constexpr int NJ = WN / 8;
    constexpr int AR = THREADS / 4;
    constexpr int BR = THREADS / 32;

    float* As = smem;
    float* Bs = smem + STAGES * TBM * PA;

    const int tid    = threadIdx.x;
    const int wid    = tid >> 5;
    const int lane   = tid & 31;
    const int g      = lane >> 2;
    const int t      = lane & 3;
    const int warp_m = wid / WARPS_N;
    const int warp_n = wid % WARPS_N;

    const int a_row = tid >> 2;
    const int a_col = (tid & 3) << 2;
    const int b_row = tid >> 5;
    const int b_col = (tid & 31) << 2;

    const int nK = (Keff + BK - 1) / BK;

    float acc[MI][NJ][4] = {};

    auto load_stage = [&](int st, int k0) {
        float* as = As + st * TBM * PA;
        float* bs = Bs + st * BK * PB;
        #pragma unroll
        for (int r = a_row; r < TBM; r += AR) {
            int kk = k0 + a_col;
            uint32_t s = (uint32_t)__cvta_generic_to_shared(&as[r * PA + a_col]);
            cp_async16(s, A + (long long)(row0 + r) * lda + kk,
                       (row0 + r < M) && (kk < Keff));
        }
        #pragma unroll
        for (int br = b_row; br < BK; br += BR) {
            int kk = k0 + br;
            uint32_t s = (uint32_t)__cvta_generic_to_shared(&bs[br * PB + b_col]);
            cp_async16(s, B + (long long)kk * N + col0 + b_col, kk < Keff);
        }
    };

    #pragma unroll
    for (int s = 0; s < STAGES - 1; s++) {
        if (s < nK) load_stage(s, s * BK);
        asm volatile("cp.async.commit_group;");
    }

    for (int it = 0; it < nK; it++) {
        asm volatile("cp.async.wait_group %0;" :: "n"(STAGES - 2));
        __syncthreads();

        int lds = it + STAGES - 1;
        if (lds < nK) load_stage(lds % STAGES, lds * BK);
        asm volatile("cp.async.commit_group;");

        const float* as = As + (it % STAGES) * TBM * PA;
        const float* bs = Bs + (it % STAGES) * BK * PB;

        #pragma unroll
        for (int k8 = 0; k8 < 2; k8++) {
            const int kb = k8 * 8;
            uint32_t af[MI][4], bf[NJ][2];
            #pragma unroll
            for (int i = 0; i < MI; i++) {
                int rb = warp_m * WM + i * 16;
                float a0 = as[(rb + g    ) * PA + kb + t    ];
                float a1 = as[(rb + g + 8) * PA + kb + t    ];
                float a2 = as[(rb + g    ) * PA + kb + t + 4];
                float a3 = as[(rb + g + 8) * PA + kb + t + 4];
                af[i][0] = RA ? f2tf32(a0) : __float_as_uint(a0);
                af[i][1] = RA ? f2tf32(a1) : __float_as_uint(a1);
                af[i][2] = RA ? f2tf32(a2) : __float_as_uint(a2);
                af[i][3] = RA ? f2tf32(a3) : __float_as_uint(a3);
            }
            #pragma unroll
            for (int j = 0; j < NJ; j++) {
                int cb = warp_n * WN + j * 8;
                float b0 = bs[(kb + t    ) * PB + cb + g];
                float b1 = bs[(kb + t + 4) * PB + cb + g];
                bf[j][0] = RB ? f2tf32(b0) : __float_as_uint(b0);
                bf[j][1] = RB ? f2tf32(b1) : __float_as_uint(b1);
            }
            #pragma unroll
            for (int i = 0; i < MI; i++)
                #pragma unroll
                for (int j = 0; j < NJ; j++)
                    mma_tf32(acc[i][j], af[i], bf[j]);
        }
        __syncthreads();
    }

    #pragma unroll
    for (int i = 0; i < MI; i++) {
        #pragma unroll
        for (int j = 0; j < NJ; j++) {
            int r = row0 + warp_m * WM + i * 16 + g;
            int c = col0 + warp_n * WN + j * 8 + 2 * t;
            if (r < M) {
                float2 v0 = make_float2(acc[i][j][0], acc[i][j][1]);
                *reinterpret_cast<float2*>(&C[(long long)r * N + c]) = v0;
            }
            if (r + 8 < M) {
                float2 v1 = make_float2(acc[i][j][2], acc[i][j][3]);
                *reinterpret_cast<float2*>(&C[(long long)(r + 8) * N + c]) = v1;
            }
        }
    }
}

// ---------------------------------------------------------------------------
// Dual launch: Wh (blocks [0,64), K=1024) + Uv split-K x4 (784 blocks, K=512).
// ---------------------------------------------------------------------------
__global__ __launch_bounds__(64)
void gemm_dual_split(const float* __restrict__ hidden, const float* __restrict__ wh_c,
                     float* __restrict__ Wh,
                     const float* __restrict__ feats, const float* __restrict__ wu_c,
                     float* __restrict__ UvP) {
    extern __shared__ float smem[];
    int bx = blockIdx.x;
    constexpr int NB_WH = (BS_ / 64) * 4;   // 64
    if (bx < NB_WH) {
        gemm_core<64, 64, 64, 64, 4, true, false>(
            hidden, wh_c, Wh, BS_, E_, H_, H_,
            (bx / 4) * 64, (bx % 4) * 128, smem);
    } else {
        bx -= NB_WH;
        int split  = bx / 196;              // 0..3
        int within = bx % 196;
        int k0     = split * (F_ / KSPLIT); // 0,512,1024,1536
        gemm_core<64, 64, 64, 64, 4, true, false>(
            feats + k0, wu_c + (long long)k0 * E_,
            UvP + (long long)split * BN_ * E_,
            BN_, E_, F_ / KSPLIT, F_,
            (within / 4) * 64, (within % 4) * 128, smem);
    }
}

// attn GEMM: batched over b, A = tf32-rounded weights, B = feats (cvt in loop)
__global__ __launch_bounds__(64)
void gemm_attn(const float* __restrict__ A, const float* __restrict__ B,
               float* __restrict__ C) {
    extern __shared__ float smem[];
    gemm_core<64, 64, 64, 64, 4, false, true>(
        A + (long long)blockIdx.z * S_ * N_,
        B + (long long)blockIdx.z * N_ * F_,
        C + (long long)blockIdx.z * S_ * F_,
        S_, F_, N_, N_,
        0, blockIdx.x * 128, smem);
}

// ---------------------------------------------------------------------------
// Pre-round w_u + w_h to tf32 (single small launch)
// ---------------------------------------------------------------------------
__global__ __launch_bounds__(256)
void cvt_b_kernel(const float4* __restrict__ wu, float4* __restrict__ wu_c,
                  const float4* __restrict__ wh, float4* __restrict__ wh_c) {
    constexpr int N1 = F_ * E_ / 4;   // 262144
    constexpr int N2 = H_ * E_ / 4;   // 131072
    int i = blockIdx.x * 256 + threadIdx.x;
    const float4* src; float4* dst;
    if (i < N1) { src = wu + i; dst = wu_c + i; }
    else if (i < N1 + N2) { src = wh + (i - N1); dst = wh_c + (i - N1); }
    else return;
    float4 v = *src;
    v.x = __uint_as_float(f2tf32(v.x));
    v.y = __uint_as_float(f2tf32(v.y));
    v.z = __uint_as_float(f2tf32(v.z));
    v.w = __uint_as_float(f2tf32(v.w));
    *dst = v;
}

// ---------------------------------------------------------------------------
// Split-K reduce: Uv = sum of 4 partials (float4)
// ---------------------------------------------------------------------------
__global__ __launch_bounds__(256)
void reduce_uv_kernel(const float4* __restrict__ p, float4* __restrict__ out) {
    constexpr int N4 = BN_ * E_ / 4;  // 401408
    int i = blockIdx.x * 256 + threadIdx.x;
    if (i >= N4) return;
    float4 a = p[i];
    float4 b = p[N4 + i];
    float4 c = p[2 * N4 + i];
    float4 d = p[3 * N4 + i];
    float4 r;
    r.x = (a.x + b.x) + (c.x + d.x);
    r.y = (a.y + b.y) + (c.y + d.y);
    r.z = (a.z + b.z) + (c.z + d.z);
    r.w = (a.w + b.w) + (c.w + d.w);
    out[i] = r;
}

// ---------------------------------------------------------------------------
// Fused scores + mask + softmax, SG=4 (256 blocks). Writes weights (+tf32 shadow).
// ---------------------------------------------------------------------------
#define SG 4

__global__ __launch_bounds__(256)
void scores_softmax_kernel(const float* __restrict__ Wh,
                           const float* __restrict__ Uv,
                           const float* __restrict__ bias,
                           const float* __restrict__ w,
                           const int* __restrict__ mask,
                           float* __restrict__ weights,
                           float* __restrict__ wts_c) {
    const int blk  = blockIdx.x;
    const int b    = blk / (S_ / SG);
    const int s0   = (blk % (S_ / SG)) * SG;
    const int tid  = threadIdx.x;
    const int warp = tid >> 5;
    const int lane = tid & 31;

    __shared__ float s_q[SG][E_];
    __shared__ float s_sc[SG][N_];
    __shared__ int   s_mask[N_];

    for (int idx = tid; idx < SG * E_; idx += 256) {
        int s = idx >> 9;
        int e = idx & (E_ - 1);
        s_q[s][e] = Wh[(long long)(b * S_ + s0 + s) * E_ + e] + bias[e];
    }
    for (int n = tid; n < N_; n += 256)
        s_mask[n] = mask[b * N_ + n];

    float wreg[16];
    #pragma unroll
    for (int j = 0; j < 16; j++)
        wreg[j] = w[lane + 32 * j];
    __syncthreads();

    for (int n = warp; n < N_; n += 8) {
        const float* uv = Uv + (long long)(b * N_ + n) * E_;
        float uvr[16];
        #pragma unroll
        for (int j = 0; j < 16; j++)
            uvr[j] = uv[lane + 32 * j];

        float acc[SG] = {};
        #pragma unroll
        for (int j = 0; j < 16; j++) {
            const float u  = uvr[j];
            const float wj = wreg[j];
            const int   e  = lane + 32 * j;
            #pragma unroll
            for (int s = 0; s < SG; s++) {
                float tv;
                asm("tanh.approx.f32 %0, %1;" : "=f"(tv) : "f"(s_q[s][e] + u));
                acc[s] = fmaf(wj, tv, acc[s]);
            }
        }
        #pragma unroll
        for (int s = 0; s < SG; s++) {
            float v = acc[s];
            #pragma unroll
            for (int off = 16; off; off >>= 1)
                v += __shfl_xor_sync(0xFFFFFFFFu, v, off);
            if (lane == 0)
                s_sc[s][n] = s_mask[n] ? v : -1e9f;
        }
    }
    __syncthreads();

    if (warp < SG) {
        const int s = warp;
        float vals[7];
        float mx = -3.4e38f;
        #pragma unroll
        for (int it = 0; it < 7; it++) {
            int n = lane + 32 * it;
            float v = (n < N_) ? s_sc[s][n] : -3.4e38f;
            vals[it] = v;
            mx = fmaxf(mx, v);
        }
        #pragma unroll
        for (int off = 16; off; off >>= 1)
            mx = fmaxf(mx, __shfl_xor_sync(0xFFFFFFFFu, mx, off));

        float sum = 0.f;
        #pragma unroll
        for (int it = 0; it < 7; it++) {
            int n = lane + 32 * it;
            float ev = (n < N_) ? __expf(vals[it] - mx) : 0.f;
            vals[it] = ev;
            sum += ev;
        }
        #pragma unroll
        for (int off = 16; off; off >>= 1)
            sum += __shfl_xor_sync(0xFFFFFFFFu, sum, off);
        float inv = 1.f / sum;

        const long long base = (long long)(b * S_ + s0 + s) * N_;
        #pragma unroll
        for (int it = 0; it < 7; it++) {
            int n = lane + 32 * it;
            if (n < N_) {
                float wv = vals[it] * inv;
                weights[base + n] = wv;
                wts_c[base + n]   = __uint_as_float(f2tf32(wv));
            }
        }
    }
}

// ---------------------------------------------------------------------------
// Launch
// ---------------------------------------------------------------------------
extern "C" void kernel_launch(void* const* d_in, const int* in_sizes, int n_in,
                              void* d_out, int out_size) {
    const float* hidden = (const float*)d_in[0];   // [16,64,1024]
    const float* feats  = (const float*)d_in[1];   // [16,196,2048]
    const int*   amask  = (const int*)  d_in[2];   // [16,196]
    const float* w_h    = (const float*)d_in[3];   // [1024,512]
    const float* w_u    = (const float*)d_in[4];   // [2048,512]
    const float* bias   = (const float*)d_in[5];   // [512]
    const float* w      = (const float*)d_in[6];   // [512]

    float* out_attn = (float*)d_out;               // [1024, 2048]
    float* out_wts  = (float*)d_out + ATTN_ELEMS;  // [1024, 196]

    float *Wh, *Uv, *UvP, *wu_c, *wh_c, *wts_c;
    cudaGetSymbolAddress((void**)&Wh,    g_Wh);
    cudaGetSymbolAddress((void**)&Uv,    g_Uv);
    cudaGetSymbolAddress((void**)&UvP,   g_UvP);
    cudaGetSymbolAddress((void**)&wu_c,  g_wu_c);
    cudaGetSymbolAddress((void**)&wh_c,  g_wh_c);
    cudaGetSymbolAddress((void**)&wts_c, g_wts_c);

    constexpr int SMEM = 4 * (64 * PA + BK * PB) * 4;  // 54272 B

    // Idempotent, stateless attribute set (no static guards — harness rule)
    cudaFuncSetAttribute(gemm_dual_split,
                         cudaFuncAttributeMaxDynamicSharedMemorySize, SMEM);
    cudaFuncSetAttribute(gemm_attn,
                         cudaFuncAttributeMaxDynamicSharedMemorySize, SMEM);

    // 0) pre-round weight matrices (w_u, w_h) to tf32
    {
        constexpr int TOT4 = (F_ * E_ + H_ * E_) / 4;   // 393216
        cvt_b_kernel<<<(TOT4 + 255) / 256, 256>>>(
            (const float4*)w_u, (float4*)wu_c,
            (const float4*)w_h, (float4*)wh_c);
    }
    // 1) dual GEMM: Wh (64 blocks) + Uv split-K x4 (784 blocks)
    {
        int nb = (BS_ / 64) * 4 + 196 * KSPLIT;   // 64 + 784 = 848
        gemm_dual_split<<<nb, 64, SMEM>>>(hidden, wh_c, Wh, feats, wu_c, UvP);
    }
    // 2) reduce split-K partials -> Uv
    {
        constexpr int N4 = BN_ * E_ / 4;
        reduce_uv_kernel<<<(N4 + 255) / 256, 256>>>((const float4*)UvP, (float4*)Uv);
    }
    // 3) fused scores + mask + softmax -> weights (+ tf32 shadow)
    scores_softmax_kernel<<<B_ * (S_ / SG), 256>>>(Wh, Uv, bias, w, amask,
                                                   out_wts, wts_c);
    // 4) attn_feats[b] = weights[b] @ feats[b]
    {
        dim3 grid(F_ / 128, 1, B_);
        gemm_attn<<<grid, 64, SMEM>>>(wts_c, feats, out_attn);
    }
}